// round 13
// baseline (speedup 1.0000x reference)
#include <cuda_runtime.h>
#include <math.h>

#define BB 64
#define SS 512
#define FF 128
#define UU 512
#define TT 511            // S-1
#define SIGD 16512        // F + F*F
#define KCAT 1152         // 128 (base) + 1024 (spline)
#define NCHUNK 43         // sig GEMM K-split (43 * 384 = 16512)
#define KCH 384

typedef unsigned long long ull;

// ---------------- scratch (static device memory; no allocations) ----------------
static __device__ float d_sig [BB*SIGD];    // [s1 | s2]
static __device__ float d_p1  [NCHUNK*BB*UU];  // sig@g_w1 partials (5.6 MB)
static __device__ float d_p2  [NCHUNK*BB*UU];  // sig@g_skip_w partials
static __device__ float d_c2  [BB*UU];
static __device__ float d_h1  [BB*UU];
static __device__ float d_h2  [BB*UU];
static __device__ float d_t3  [BB*UU];
static __device__ float d_t4  [BB*UU];
static __device__ float d_agg [BB*KCAT];    // [sum w*silu(x) | sum w*bspl(x)]
static __device__ float d_cur [BB*UU];
static __device__ float d_Wcat[KCAT*UU];    // [base_w ; spline_w^T]
static __device__ float d_g4  [4*BB*UU];    // gates f,i,c,o pre-activation

// ---------------- helpers ----------------
__device__ __forceinline__ float sigm(float x) {
    return __fdividef(1.f, 1.f + __expf(-x));
}
__device__ __forceinline__ void fma2(ull &d, ull a, ull b) {
    asm("fma.rn.f32x2 %0, %1, %2, %0;" : "+l"(d) : "l"(a), "l"(b));
}
__device__ __forceinline__ ull splat2(float x) {
    ull r; asm("mov.b64 %0, {%1, %1};" : "=l"(r) : "f"(x)); return r;
}
__device__ __forceinline__ void unpack2(ull v, float &lo, float &hi) {
    asm("mov.b64 {%0, %1}, %2;" : "=f"(lo), "=f"(hi) : "l"(v));
}

// cubic B-spline basis (GRID_SIZE=5, ORDER=3); denominators constant-fold
__device__ __forceinline__ void bspline8(float x, float bs[8]) {
    float g[12];
#pragma unroll
    for (int j = 0; j < 12; ++j) g[j] = -1.0f + 0.4f * (float)(j - 3);
    float b0[11];
#pragma unroll
    for (int j = 0; j < 11; ++j) b0[j] = (x >= g[j] && x < g[j + 1]) ? 1.f : 0.f;
#pragma unroll
    for (int p = 1; p <= 3; ++p) {
#pragma unroll
        for (int j = 0; j + p < 11; ++j) {
            float left  = (x - g[j])       * (1.0f / (g[j + p] - g[j]));
            float right = (g[j + p + 1]-x) * (1.0f / (g[j + p + 1] - g[j + 1]));
            b0[j] = left * b0[j] + right * b0[j + 1];
        }
    }
#pragma unroll
    for (int k = 0; k < 8; ++k) bs[k] = b0[k];
}

// ---------------- merged init: zero + h2<-b2 + Wcat build ----------------
// grid 1560 blocks of 256: [0,1032) zero, [1032,1544) transpose, [1544,1560) copy
__global__ void init_kernel(const float* __restrict__ b2,
                            const float* __restrict__ sw,
                            const float* __restrict__ bw) {
    __shared__ float tile[32][33];
    int bid = blockIdx.x;
    if (bid < 1032) {
        int i = bid * 256 + threadIdx.x;
        float4 z = make_float4(0.f, 0.f, 0.f, 0.f);
        if (i < BB * SIGD / 4) ((float4*)d_sig)[i] = z;
        if (i < BB * UU / 4) {
            ((float4*)d_t3)[i] = z; ((float4*)d_t4)[i] = z; ((float4*)d_cur)[i] = z;
            ((float4*)d_c2)[i] = z; ((float4*)d_h1)[i] = z;
        }
        if (i < 4 * BB * UU / 4) ((float4*)d_g4)[i] = z;
        if (i < BB * KCAT / 4) ((float4*)d_agg)[i] = z;
        if (i < BB * UU) d_h2[i] = b2[i & 511];
    } else {
        int pid = bid - 1032;
        int tx = threadIdx.x & 31, ty = threadIdx.x >> 5;
        if (pid < 512) {
            int fk0 = (pid & 31) * 32, u0 = (pid >> 5) * 32;
            for (int r = ty; r < 32; r += 8)
                tile[r][tx] = sw[(size_t)(u0 + r) * 1024 + fk0 + tx];
            __syncthreads();
            for (int r = ty; r < 32; r += 8)
                d_Wcat[(size_t)(128 + fk0 + r) * UU + u0 + tx] = tile[tx][r];
        } else {
            int base = (pid - 512) * 4096;
            for (int i = threadIdx.x; i < 4096; i += 256)
                d_Wcat[base + i] = bw[base + i];
        }
    }
}

// ---------------- scan-free signature kernel (full 128-col tiles) ------------
// A_t = 0.5(x_t + x_{t+1}) - x_0 ; B_t = x_{t+1} - x_t ; s2 += A_t (x) B_t
// grid (64 b, 4 tseg), block 256; per-thread 8 rows (4 f32x2 pairs) x 8 cols
__global__ void s2p_kernel(const float* __restrict__ in,
                           const float* __restrict__ tk) {
    __shared__ __align__(16) float xc[16][FF];
    __shared__ __align__(16) float Ak[16][FF];
    __shared__ __align__(16) float Bk[16][FF];
    __shared__ float x0s[FF], xprev[FF];
    __shared__ float tks[SS];
    int b  = blockIdx.x;
    int t0 = blockIdx.y * 128;
    int tlim = min(TT, t0 + 128);
    int tid = threadIdx.x;
    int tx = tid & 15, ty = tid >> 4;
    const float* ib = in + (size_t)b * SS * FF;

    for (int i = tid; i < SS; i += 256) tks[i] = tk[i];
    __syncthreads();
    if (tid < FF) {
        x0s[tid]   = tks[0]  * ib[tid];
        xprev[tid] = tks[t0] * ib[(size_t)t0 * FF + tid];
    }
    __syncthreads();

    ull acc[4][8];
#pragma unroll
    for (int r = 0; r < 4; ++r)
#pragma unroll
        for (int c = 0; c < 8; ++c) acc[r][c] = 0ULL;

    for (int cch = 0; cch < 8; ++cch) {
        int tbase = t0 + cch * 16;
#pragma unroll
        for (int s = 0; s < 8; ++s) {
            int e = tid + s * 256;
            int kk = e >> 7, f = e & 127;
            int t1 = tbase + kk + 1;
            xc[kk][f] = (t1 < SS) ? tks[t1] * ib[(size_t)t1 * FF + f] : 0.f;
        }
        __syncthreads();
#pragma unroll
        for (int s = 0; s < 8; ++s) {
            int e = tid + s * 256;
            int kk = e >> 7, f = e & 127;
            float prev = kk ? xc[kk - 1][f] : xprev[f];
            float cur = xc[kk][f];
            bool valid = (tbase + kk) < tlim;
            Bk[kk][f] = valid ? (cur - prev) : 0.f;
            Ak[kk][f] = 0.5f * (prev + cur) - x0s[f];
        }
        if (tid < FF) xprev[tid] = xc[15][tid];
        __syncthreads();
#pragma unroll
        for (int kk = 0; kk < 16; ++kk) {
            const ull* ap = (const ull*)(&Ak[kk][ty * 8]);
            ull a2[4];
#pragma unroll
            for (int r = 0; r < 4; ++r) a2[r] = ap[r];
#pragma unroll
            for (int c = 0; c < 8; ++c) {
                ull dsp = splat2(Bk[kk][tx + 16 * c]);
#pragma unroll
                for (int r = 0; r < 4; ++r) fma2(acc[r][c], a2[r], dsp);
            }
        }
        __syncthreads();
    }

    float* out = d_sig + (size_t)b * SIGD + FF;
#pragma unroll
    for (int r = 0; r < 4; ++r)
#pragma unroll
        for (int c = 0; c < 8; ++c) {
            float lo, hi; unpack2(acc[r][c], lo, hi);
            int i = ty * 8 + 2 * r;
            int j = tx + 16 * c;
            atomicAdd(&out[(size_t)i * FF + j], lo);
            atomicAdd(&out[(size_t)(i + 1) * FF + j], hi);
        }
    // s1 = x[S-1] - x[0]
    if (blockIdx.y == 0 && tid < FF)
        d_sig[(size_t)b * SIGD + tid] = tks[SS - 1] * ib[(size_t)(SS - 1) * FF + tid] - x0s[tid];
}

// ---------------- sig GEMM: double-buffered smem, single sync per block ------
// grid (4 jtile, NCHUNK kchunk, 2 which) = 344 CTAs, 3 CTAs/SM -> single wave.
__global__ void __launch_bounds__(256, 3)
gemm_sig(const float* __restrict__ A,
         const float* __restrict__ W1, const float* __restrict__ W2,
         float* __restrict__ P1, float* __restrict__ P2) {
    __shared__ __align__(16) ull  As2[2][64][18];
    __shared__ __align__(16) float Ws[2][16][128];
    int tid = threadIdx.x;
    int tx = tid & 15, ty = tid >> 4;
    int j0 = blockIdx.x * 128;
    int kbeg = blockIdx.y * KCH;
    const float* W = blockIdx.z ? W2 : W1;
    float* P = (blockIdx.z ? P2 : P1) + (size_t)blockIdx.y * BB * UU;
    int arow = tid >> 2, akq = (tid & 3) * 4;
    int wkk = tid >> 5, wjq = (tid & 31) * 4;

    ull acc[4][4];
#pragma unroll
    for (int r = 0; r < 4; ++r)
#pragma unroll
        for (int c = 0; c < 4; ++c) acc[r][c] = 0ULL;

    {
        float4 va = *(const float4*)(A + (size_t)arow * SIGD + kbeg + akq);
        float4 w0 = *(const float4*)(W + (size_t)(kbeg + wkk)     * UU + j0 + wjq);
        float4 w1 = *(const float4*)(W + (size_t)(kbeg + wkk + 8) * UU + j0 + wjq);
        As2[0][arow][akq]     = splat2(va.x);
        As2[0][arow][akq + 1] = splat2(va.y);
        As2[0][arow][akq + 2] = splat2(va.z);
        As2[0][arow][akq + 3] = splat2(va.w);
        *(float4*)&Ws[0][wkk][wjq]     = w0;
        *(float4*)&Ws[0][wkk + 8][wjq] = w1;
    }
    __syncthreads();
    int buf = 0;
    for (int k0 = kbeg; k0 < kbeg + KCH; k0 += 16) {
        float4 va, w0, w1;
        bool more = (k0 + 16) < kbeg + KCH;
        if (more) {
            int kn = k0 + 16;
            va = *(const float4*)(A + (size_t)arow * SIGD + kn + akq);
            w0 = *(const float4*)(W + (size_t)(kn + wkk)     * UU + j0 + wjq);
            w1 = *(const float4*)(W + (size_t)(kn + wkk + 8) * UU + j0 + wjq);
        }
#pragma unroll
        for (int kk = 0; kk < 16; ++kk) {
            ull w2[4];
#pragma unroll
            for (int c = 0; c < 4; ++c)
                w2[c] = *(const ull*)(&Ws[buf][kk][tx * 2 + 32 * c]);
#pragma unroll
            for (int r = 0; r < 4; ++r) {
                ull asp = As2[buf][ty * 4 + r][kk];
#pragma unroll
                for (int c = 0; c < 4; ++c) fma2(acc[r][c], asp, w2[c]);
            }
        }
        if (more) {
            int nb = buf ^ 1;
            As2[nb][arow][akq]     = splat2(va.x);
            As2[nb][arow][akq + 1] = splat2(va.y);
            As2[nb][arow][akq + 2] = splat2(va.z);
            As2[nb][arow][akq + 3] = splat2(va.w);
            *(float4*)&Ws[nb][wkk][wjq]     = w0;
            *(float4*)&Ws[nb][wkk + 8][wjq] = w1;
        }
        __syncthreads();
        buf ^= 1;
    }
#pragma unroll
    for (int r = 0; r < 4; ++r)
#pragma unroll
        for (int c = 0; c < 4; ++c) {
            int row = ty * 4 + r;
            int col = j0 + tx * 2 + 32 * c;
            *(ull*)(&P[(size_t)row * UU + col]) = acc[r][c];
        }
}

// ---------------- reduce partials, 4-way plane split + atomics ---------------
// grid (128, 4), block 256: quarter q sums planes [q*11, min(43,q*11+11))
__global__ void reduce_split() {
    int i = blockIdx.x * blockDim.x + threadIdx.x;   // 0..32767
    int q = blockIdx.y;
    int pbeg = q * 11, pend = min(NCHUNK, pbeg + 11);
    float s1 = 0.f, s2 = 0.f;
    for (int p = pbeg; p < pend; ++p) {
        s1 += d_p1[(size_t)p * BB * UU + i];
        s2 += d_p2[(size_t)p * BB * UU + i];
    }
    atomicAdd(&d_h1[i], s1);
    atomicAdd(&d_c2[i], s2);
}

// elu in place: h1 = elu(h1 + b1). grid 128, block 256
__global__ void elu_kernel(const float* __restrict__ b1) {
    int i = blockIdx.x * blockDim.x + threadIdx.x;
    float v = d_h1[i] + b1[i & 511];
    d_h1[i] = v > 0.f ? v : expm1f(v);
}

// ---------------- 64xN GEMM core (atomic version, for small GEMMs) ----------
#define KC 16
__device__ __forceinline__ void gemm_core(const float* __restrict__ A, int lda,
                                          const float* __restrict__ W,
                                          float* __restrict__ C,
                                          int kbeg, int kend) {
    __shared__ __align__(16) float As[64][20];
    __shared__ __align__(16) float Ws[KC][128];
    int tid = threadIdx.x;
    int tx = tid & 15, ty = tid >> 4;
    int j0 = blockIdx.x * 128;
    int arow = tid >> 2, akq = (tid & 3) * 4;
    int wkk = tid >> 5, wjq = (tid & 31) * 4;
    ull acc[4][4];
#pragma unroll
    for (int r = 0; r < 4; ++r)
#pragma unroll
        for (int c = 0; c < 4; ++c) acc[r][c] = 0ULL;

    {
        float4 va = *(const float4*)(A + (size_t)arow * lda + kbeg + akq);
        float4 w0 = *(const float4*)(W + (size_t)(kbeg + wkk)     * UU + j0 + wjq);
        float4 w1 = *(const float4*)(W + (size_t)(kbeg + wkk + 8) * UU + j0 + wjq);
        *(float4*)&As[arow][akq]   = va;
        *(float4*)&Ws[wkk][wjq]    = w0;
        *(float4*)&Ws[wkk + 8][wjq] = w1;
    }
    __syncthreads();
    for (int k0 = kbeg; k0 < kend; k0 += KC) {
        float4 va, w0, w1;
        bool more = (k0 + KC) < kend;
        if (more) {
            int kn = k0 + KC;
            va = *(const float4*)(A + (size_t)arow * lda + kn + akq);
            w0 = *(const float4*)(W + (size_t)(kn + wkk)     * UU + j0 + wjq);
            w1 = *(const float4*)(W + (size_t)(kn + wkk + 8) * UU + j0 + wjq);
        }
#pragma unroll
        for (int kk = 0; kk < KC; ++kk) {
            const ull* wp = (const ull*)(&Ws[kk][tx * 8]);
            ull w2[4];
#pragma unroll
            for (int c = 0; c < 4; ++c) w2[c] = wp[c];
#pragma unroll
            for (int r = 0; r < 4; ++r) {
                ull asp = splat2(As[ty * 4 + r][kk]);
#pragma unroll
                for (int c = 0; c < 4; ++c) fma2(acc[r][c], asp, w2[c]);
            }
        }
        __syncthreads();
        if (more) {
            *(float4*)&As[arow][akq]    = va;
            *(float4*)&Ws[wkk][wjq]     = w0;
            *(float4*)&Ws[wkk + 8][wjq] = w1;
        }
        __syncthreads();
    }
#pragma unroll
    for (int r = 0; r < 4; ++r)
#pragma unroll
        for (int c = 0; c < 4; ++c) {
            float lo, hi; unpack2(acc[r][c], lo, hi);
            int row = ty * 4 + r;
            int col = j0 + tx * 8 + 2 * c;
            atomicAdd(&C[(size_t)row * UU + col], lo);
            atomicAdd(&C[(size_t)row * UU + col + 1], hi);
        }
}

__global__ void gemm_one(const float* __restrict__ A, int lda,
                         const float* __restrict__ W,
                         float* __restrict__ C, int K) {
    int kchunk = K / gridDim.y;
    gemm_core(A, lda, W, C, kchunk * blockIdx.y, kchunk * (blockIdx.y + 1));
}

__global__ void gemm_two(const float* __restrict__ A, int lda,
                         const float* __restrict__ W1, const float* __restrict__ W2,
                         float* __restrict__ C1, float* __restrict__ C2, int K) {
    int kchunk = K / gridDim.y;
    const float* W = blockIdx.z ? W2 : W1;
    float* C = blockIdx.z ? C2 : C1;
    gemm_core(A, lda, W, C, kchunk * blockIdx.y, kchunk * (blockIdx.y + 1));
}

__global__ void gemm_gates(const float* __restrict__ cur,
                           const float* __restrict__ hprev,
                           const float* __restrict__ wf, const float* __restrict__ wi,
                           const float* __restrict__ wc, const float* __restrict__ wo,
                           float* __restrict__ g4) {
    int kb = blockIdx.y * 64, ke = kb + 64;
    const float* Wg = (blockIdx.z == 0) ? wf : (blockIdx.z == 1) ? wi
                    : (blockIdx.z == 2) ? wc : wo;
    const float* A = (kb < 512) ? cur : (hprev - 512);
    gemm_core(A, UU, Wg, g4 + (size_t)blockIdx.z * BB * UU, kb, ke);
}

// ---------------- agg + inlined GLU/LN/softmax -------------------------------
// grid (64 b, 8 s-chunks), block 128. Each CTA redoes the cheap LN+softmax
// for its batch row (deterministic, removes lnsm kernel + attn round-trip).
__global__ void agg_kernel(const float* __restrict__ in,
                           const float* __restrict__ tk,
                           const float* __restrict__ b3,
                           const float* __restrict__ b4,
                           const float* __restrict__ bskip,
                           const float* __restrict__ gamma,
                           const float* __restrict__ beta) {
    __shared__ float ys[UU];
    __shared__ float red[128];
    __shared__ float ws[64], tks[64];
    int b = blockIdx.x;
    int s0 = blockIdx.y * 64;
    int tid = threadIdx.x;

    // GLU
    float y[4];
#pragma unroll
    for (int q = 0; q < 4; ++q) {
        int u = tid + 128 * q, i = b * UU + u;
        float g = sigm(d_t3[i] + b3[u]);
        y[q] = d_c2[i] + bskip[u] + g * (d_t4[i] + b4[u]);
    }
    // mean
    red[tid] = y[0] + y[1] + y[2] + y[3];
    __syncthreads();
    for (int s = 64; s > 0; s >>= 1) { if (tid < s) red[tid] += red[tid + s]; __syncthreads(); }
    float mu = red[0] * (1.f / 512.f);
    __syncthreads();
    // var
    float v = 0.f;
#pragma unroll
    for (int q = 0; q < 4; ++q) { float d = y[q] - mu; v += d * d; }
    red[tid] = v;
    __syncthreads();
    for (int s = 64; s > 0; s >>= 1) { if (tid < s) red[tid] += red[tid + s]; __syncthreads(); }
    float rs = rsqrtf(red[0] * (1.f / 512.f) + 1e-3f);
    __syncthreads();
    // normalized values + max
    float m = -1e30f;
#pragma unroll
    for (int q = 0; q < 4; ++q) {
        int u = tid + 128 * q;
        float yn = (y[q] - mu) * rs * gamma[u] + beta[u];
        ys[u] = yn;
        m = fmaxf(m, yn);
    }
    red[tid] = m;
    __syncthreads();
    for (int s = 64; s > 0; s >>= 1) { if (tid < s) red[tid] = fmaxf(red[tid], red[tid + s]); __syncthreads(); }
    float M = red[0];
    __syncthreads();
    // exp sum
    float es = 0.f;
#pragma unroll
    for (int q = 0; q < 4; ++q) es += __expf(ys[tid + 128 * q] - M);
    red[tid] = es;
    __syncthreads();
    for (int s = 64; s > 0; s >>= 1) { if (tid < s) red[tid] += red[tid + s]; __syncthreads(); }
    float inv = __fdividef(1.f, red[0] * 512.f);   // softmax / S

    if (tid < 64) {
        ws[tid]  = __expf(ys[s0 + tid] - M) * inv;
        tks[tid] = tk[s0 + tid];
    }
    __syncthreads();

    // aggregation
    int f = tid;
    float sacc = 0.f;
    float bacc[8] = {};
    const float* ip = in + (size_t)b * SS * FF + (size_t)s0 * FF + f;
    for (int si = 0; si < 64; ++si) {
        float x = tks[si] * ip[si * FF];
        float w = ws[si];
        float sg = sigm(x);
        sacc += w * (x * sg);
        float bs[8];
        bspline8(x, bs);
#pragma unroll
        for (int k = 0; k < 8; ++k) bacc[k] += w * bs[k];
    }
    atomicAdd(&d_agg[b * KCAT + f], sacc);
#pragma unroll
    for (int k = 0; k < 8; ++k)
        atomicAdd(&d_agg[b * KCAT + 128 + f * 8 + k], bacc[k]);
}

// ---------------- final LSTM cell ----------------
__global__ void lstm_kernel(const float* __restrict__ c_prev,
                            const float* __restrict__ bf,
                            const float* __restrict__ bi_,
                            const float* __restrict__ bc,
                            const float* __restrict__ bo,
                            float* __restrict__ out) {
    int i = blockIdx.x * blockDim.x + threadIdx.x;
    int u = i & 511;
    float f  = sigm(d_g4[i]            + bf [u]);
    float ig = sigm(d_g4[BB*UU + i]    + bi_[u]);
    float cd = tanhf(d_g4[2*BB*UU + i] + bc [u]);
    float o  = sigm(d_g4[3*BB*UU + i]  + bo [u]);
    float cn = f * c_prev[i] + ig * cd;
    out[i] = o * tanhf(cn);
    out[BB*UU + i] = cn;
}

// ---------------- host ----------------
extern "C" void kernel_launch(void* const* d_in, const int* in_sizes, int n_in,
                              void* d_out, int out_size) {
    const float* in       = (const float*)d_in[0];
    const float* h_prev   = (const float*)d_in[1];
    const float* c_prev   = (const float*)d_in[2];
    const float* tk       = (const float*)d_in[3];
    const float* base_w   = (const float*)d_in[4];
    const float* spline_w = (const float*)d_in[5];
    const float* g_w1     = (const float*)d_in[6];
    const float* g_b1     = (const float*)d_in[7];
    const float* g_w2     = (const float*)d_in[8];
    const float* g_b2     = (const float*)d_in[9];
    const float* g_w3     = (const float*)d_in[10];
    const float* g_b3     = (const float*)d_in[11];
    const float* g_w4     = (const float*)d_in[12];
    const float* g_b4     = (const float*)d_in[13];
    const float* g_skip_w = (const float*)d_in[14];
    const float* g_skip_b = (const float*)d_in[15];
    const float* ln_gamma = (const float*)d_in[16];
    const float* ln_beta  = (const float*)d_in[17];
    const float* wf       = (const float*)d_in[18];
    const float* bf       = (const float*)d_in[19];
    const float* wi       = (const float*)d_in[20];
    const float* bi       = (const float*)d_in[21];
    const float* wc       = (const float*)d_in[22];
    const float* bc       = (const float*)d_in[23];
    const float* wo       = (const float*)d_in[24];
    const float* bo       = (const float*)d_in[25];
    float* out = (float*)d_out;
    (void)in_sizes; (void)n_in; (void)out_size;

    float *p_sig, *p_p1, *p_p2, *p_h1, *p_h2, *p_t3, *p_t4;
    float *p_agg, *p_cur, *p_Wcat, *p_g4;
    cudaGetSymbolAddress((void**)&p_sig,  d_sig);
    cudaGetSymbolAddress((void**)&p_p1,   d_p1);
    cudaGetSymbolAddress((void**)&p_p2,   d_p2);
    cudaGetSymbolAddress((void**)&p_h1,   d_h1);
    cudaGetSymbolAddress((void**)&p_h2,   d_h2);
    cudaGetSymbolAddress((void**)&p_t3,   d_t3);
    cudaGetSymbolAddress((void**)&p_t4,   d_t4);
    cudaGetSymbolAddress((void**)&p_agg,  d_agg);
    cudaGetSymbolAddress((void**)&p_cur,  d_cur);
    cudaGetSymbolAddress((void**)&p_Wcat, d_Wcat);
    cudaGetSymbolAddress((void**)&p_g4,   d_g4);

    init_kernel<<<1560, 256>>>(g_b2, spline_w, base_w);
    s2p_kernel<<<dim3(64, 4), 256>>>(in, tk);

    // sig @ g_w1 and sig @ g_skip_w -> partial planes (344 CTAs, single wave)
    gemm_sig<<<dim3(4, NCHUNK, 2), 256>>>(p_sig, g_w1, g_skip_w, p_p1, p_p2);
    reduce_split<<<dim3(128, 4), 256>>>();
    elu_kernel<<<128, 256>>>(g_b1);

    gemm_one<<<dim3(4, 32), 256>>>(p_h1, UU, g_w2, p_h2, UU);           // h2 += h1@W2 (b2 pre-set)
    gemm_two<<<dim3(4, 32, 2), 256>>>(p_h2, UU, g_w3, g_w4, p_t3, p_t4, UU);

    agg_kernel<<<dim3(64, 8), 128>>>(in, tk, g_b3, g_b4, g_skip_b, ln_gamma, ln_beta);

    // current = [aggs|aggb] @ [base_w; spline_w^T]  (K=1152, 36 chunks of 32)
    gemm_one<<<dim3(4, 36), 256>>>(p_agg, KCAT, p_Wcat, p_cur, KCAT);

    // gates: combined = [current | h_prev], kchunk 64
    gemm_gates<<<dim3(4, 16, 4), 256>>>(p_cur, h_prev, wf, wi, wc, wo, p_g4);

    lstm_kernel<<<128, 256>>>(c_prev, bf, bi, bc, bo, out);
}

// round 14
// speedup vs baseline: 1.5245x; 1.5245x over previous
#include <cuda_runtime.h>
#include <math.h>

#define BB 64
#define SS 512
#define FF 128
#define UU 512
#define TT 511            // S-1
#define SIGD 16512        // F + F*F
#define KCAT 1152         // 128 (base) + 1024 (spline)
#define NCHUNK 43         // sig GEMM K-split (43 * 384 = 16512)
#define KCH 384

typedef unsigned long long ull;

// ---------------- scratch (static device memory; no allocations) ----------------
static __device__ float d_sig [BB*SIGD];    // [s1 | s2]
static __device__ float d_p1  [NCHUNK*BB*UU];  // sig@g_w1 partials (5.6 MB)
static __device__ float d_p2  [NCHUNK*BB*UU];  // sig@g_skip_w partials
static __device__ float d_c2  [BB*UU];
static __device__ float d_h1  [BB*UU];
static __device__ float d_h2  [BB*UU];
static __device__ float d_t3  [BB*UU];
static __device__ float d_t4  [BB*UU];
static __device__ float d_agg [BB*KCAT];    // [sum w*silu(x) | sum w*bspl(x)]
static __device__ float d_cur [BB*UU];
static __device__ float d_Wcat[KCAT*UU];    // [base_w ; spline_w^T]
static __device__ float d_g4  [4*BB*UU];    // gates f,i,c,o pre-activation

// ---------------- helpers ----------------
__device__ __forceinline__ float sigm(float x) {
    return __fdividef(1.f, 1.f + __expf(-x));
}
__device__ __forceinline__ void fma2(ull &d, ull a, ull b) {
    asm("fma.rn.f32x2 %0, %1, %2, %0;" : "+l"(d) : "l"(a), "l"(b));
}
__device__ __forceinline__ ull splat2(float x) {
    ull r; asm("mov.b64 %0, {%1, %1};" : "=l"(r) : "f"(x)); return r;
}
__device__ __forceinline__ void unpack2(ull v, float &lo, float &hi) {
    asm("mov.b64 {%0, %1}, %2;" : "=f"(lo), "=f"(hi) : "l"(v));
}

// cubic B-spline basis (GRID_SIZE=5, ORDER=3); denominators constant-fold
__device__ __forceinline__ void bspline8(float x, float bs[8]) {
    float g[12];
#pragma unroll
    for (int j = 0; j < 12; ++j) g[j] = -1.0f + 0.4f * (float)(j - 3);
    float b0[11];
#pragma unroll
    for (int j = 0; j < 11; ++j) b0[j] = (x >= g[j] && x < g[j + 1]) ? 1.f : 0.f;
#pragma unroll
    for (int p = 1; p <= 3; ++p) {
#pragma unroll
        for (int j = 0; j + p < 11; ++j) {
            float left  = (x - g[j])       * (1.0f / (g[j + p] - g[j]));
            float right = (g[j + p + 1]-x) * (1.0f / (g[j + p + 1] - g[j + 1]));
            b0[j] = left * b0[j] + right * b0[j + 1];
        }
    }
#pragma unroll
    for (int k = 0; k < 8; ++k) bs[k] = b0[k];
}

// ---------------- merged init: zero + h2<-b2 + Wcat build ----------------
// grid 1560 blocks of 256: [0,1032) zero, [1032,1544) transpose, [1544,1560) copy
__global__ void init_kernel(const float* __restrict__ b2,
                            const float* __restrict__ sw,
                            const float* __restrict__ bw) {
    __shared__ float tile[32][33];
    int bid = blockIdx.x;
    if (bid < 1032) {
        int i = bid * 256 + threadIdx.x;
        float4 z = make_float4(0.f, 0.f, 0.f, 0.f);
        if (i < BB * SIGD / 4) ((float4*)d_sig)[i] = z;
        if (i < BB * UU / 4) {
            ((float4*)d_t3)[i] = z; ((float4*)d_t4)[i] = z; ((float4*)d_cur)[i] = z;
            ((float4*)d_c2)[i] = z; ((float4*)d_h1)[i] = z;
        }
        if (i < 4 * BB * UU / 4) ((float4*)d_g4)[i] = z;
        if (i < BB * KCAT / 4) ((float4*)d_agg)[i] = z;
        if (i < BB * UU) d_h2[i] = b2[i & 511];
    } else {
        int pid = bid - 1032;
        int tx = threadIdx.x & 31, ty = threadIdx.x >> 5;
        if (pid < 512) {
            int fk0 = (pid & 31) * 32, u0 = (pid >> 5) * 32;
            for (int r = ty; r < 32; r += 8)
                tile[r][tx] = sw[(size_t)(u0 + r) * 1024 + fk0 + tx];
            __syncthreads();
            for (int r = ty; r < 32; r += 8)
                d_Wcat[(size_t)(128 + fk0 + r) * UU + u0 + tx] = tile[tx][r];
        } else {
            int base = (pid - 512) * 4096;
            for (int i = threadIdx.x; i < 4096; i += 256)
                d_Wcat[base + i] = bw[base + i];
        }
    }
}

// ---------------- scan-free signature kernel (full 128-col tiles) ------------
// A_t = 0.5(x_t + x_{t+1}) - x_0 ; B_t = x_{t+1} - x_t ; s2 += A_t (x) B_t
// grid (64 b, 4 tseg), block 256; per-thread 8 rows (4 f32x2 pairs) x 8 cols
__global__ void s2p_kernel(const float* __restrict__ in,
                           const float* __restrict__ tk) {
    __shared__ __align__(16) float xc[16][FF];
    __shared__ __align__(16) float Ak[16][FF];
    __shared__ __align__(16) float Bk[16][FF];
    __shared__ float x0s[FF], xprev[FF];
    __shared__ float tks[SS];
    int b  = blockIdx.x;
    int t0 = blockIdx.y * 128;
    int tlim = min(TT, t0 + 128);
    int tid = threadIdx.x;
    int tx = tid & 15, ty = tid >> 4;
    const float* ib = in + (size_t)b * SS * FF;

    for (int i = tid; i < SS; i += 256) tks[i] = tk[i];
    __syncthreads();
    if (tid < FF) {
        x0s[tid]   = tks[0]  * ib[tid];
        xprev[tid] = tks[t0] * ib[(size_t)t0 * FF + tid];
    }
    __syncthreads();

    ull acc[4][8];
#pragma unroll
    for (int r = 0; r < 4; ++r)
#pragma unroll
        for (int c = 0; c < 8; ++c) acc[r][c] = 0ULL;

    for (int cch = 0; cch < 8; ++cch) {
        int tbase = t0 + cch * 16;
#pragma unroll
        for (int s = 0; s < 8; ++s) {
            int e = tid + s * 256;
            int kk = e >> 7, f = e & 127;
            int t1 = tbase + kk + 1;
            xc[kk][f] = (t1 < SS) ? tks[t1] * ib[(size_t)t1 * FF + f] : 0.f;
        }
        __syncthreads();
#pragma unroll
        for (int s = 0; s < 8; ++s) {
            int e = tid + s * 256;
            int kk = e >> 7, f = e & 127;
            float prev = kk ? xc[kk - 1][f] : xprev[f];
            float cur = xc[kk][f];
            bool valid = (tbase + kk) < tlim;
            Bk[kk][f] = valid ? (cur - prev) : 0.f;
            Ak[kk][f] = 0.5f * (prev + cur) - x0s[f];
        }
        if (tid < FF) xprev[tid] = xc[15][tid];
        __syncthreads();
#pragma unroll
        for (int kk = 0; kk < 16; ++kk) {
            const ull* ap = (const ull*)(&Ak[kk][ty * 8]);
            ull a2[4];
#pragma unroll
            for (int r = 0; r < 4; ++r) a2[r] = ap[r];
#pragma unroll
            for (int c = 0; c < 8; ++c) {
                ull dsp = splat2(Bk[kk][tx + 16 * c]);
#pragma unroll
                for (int r = 0; r < 4; ++r) fma2(acc[r][c], a2[r], dsp);
            }
        }
        __syncthreads();
    }

    float* out = d_sig + (size_t)b * SIGD + FF;
#pragma unroll
    for (int r = 0; r < 4; ++r)
#pragma unroll
        for (int c = 0; c < 8; ++c) {
            float lo, hi; unpack2(acc[r][c], lo, hi);
            int i = ty * 8 + 2 * r;
            int j = tx + 16 * c;
            atomicAdd(&out[(size_t)i * FF + j], lo);
            atomicAdd(&out[(size_t)(i + 1) * FF + j], hi);
        }
    // s1 = x[S-1] - x[0]
    if (blockIdx.y == 0 && tid < FF)
        d_sig[(size_t)b * SIGD + tid] = tks[SS - 1] * ib[(size_t)(SS - 1) * FF + tid] - x0s[tid];
}

// ---------------- sig GEMM: single-buffer (round-10/12 proven) ---------------
// grid (4 jtile, NCHUNK kchunk, 2 which) = 344 CTAs, 3 CTAs/SM -> single wave.
__global__ void __launch_bounds__(256, 3)
gemm_sig(const float* __restrict__ A,
         const float* __restrict__ W1, const float* __restrict__ W2,
         float* __restrict__ P1, float* __restrict__ P2) {
    __shared__ __align__(16) ull  As2[64][18];
    __shared__ __align__(16) float Ws[16][128];
    int tid = threadIdx.x;
    int tx = tid & 15, ty = tid >> 4;
    int j0 = blockIdx.x * 128;
    int kbeg = blockIdx.y * KCH;
    const float* W = blockIdx.z ? W2 : W1;
    float* P = (blockIdx.z ? P2 : P1) + (size_t)blockIdx.y * BB * UU;
    int arow = tid >> 2, akq = (tid & 3) * 4;
    int wkk = tid >> 5, wjq = (tid & 31) * 4;

    ull acc[4][4];
#pragma unroll
    for (int r = 0; r < 4; ++r)
#pragma unroll
        for (int c = 0; c < 4; ++c) acc[r][c] = 0ULL;

    {
        float4 va = *(const float4*)(A + (size_t)arow * SIGD + kbeg + akq);
        float4 w0 = *(const float4*)(W + (size_t)(kbeg + wkk)     * UU + j0 + wjq);
        float4 w1 = *(const float4*)(W + (size_t)(kbeg + wkk + 8) * UU + j0 + wjq);
        As2[arow][akq]     = splat2(va.x);
        As2[arow][akq + 1] = splat2(va.y);
        As2[arow][akq + 2] = splat2(va.z);
        As2[arow][akq + 3] = splat2(va.w);
        *(float4*)&Ws[wkk][wjq]     = w0;
        *(float4*)&Ws[wkk + 8][wjq] = w1;
    }
    __syncthreads();
    for (int k0 = kbeg; k0 < kbeg + KCH; k0 += 16) {
        float4 va, w0, w1;
        bool more = (k0 + 16) < kbeg + KCH;
        if (more) {
            int kn = k0 + 16;
            va = *(const float4*)(A + (size_t)arow * SIGD + kn + akq);
            w0 = *(const float4*)(W + (size_t)(kn + wkk)     * UU + j0 + wjq);
            w1 = *(const float4*)(W + (size_t)(kn + wkk + 8) * UU + j0 + wjq);
        }
#pragma unroll
        for (int kk = 0; kk < 16; ++kk) {
            ull w2[4];
#pragma unroll
            for (int c = 0; c < 4; ++c)
                w2[c] = *(const ull*)(&Ws[kk][tx * 2 + 32 * c]);
#pragma unroll
            for (int r = 0; r < 4; ++r) {
                ull asp = As2[ty * 4 + r][kk];
#pragma unroll
                for (int c = 0; c < 4; ++c) fma2(acc[r][c], asp, w2[c]);
            }
        }
        __syncthreads();
        if (more) {
            As2[arow][akq]     = splat2(va.x);
            As2[arow][akq + 1] = splat2(va.y);
            As2[arow][akq + 2] = splat2(va.z);
            As2[arow][akq + 3] = splat2(va.w);
            *(float4*)&Ws[wkk][wjq]     = w0;
            *(float4*)&Ws[wkk + 8][wjq] = w1;
        }
        __syncthreads();
    }
#pragma unroll
    for (int r = 0; r < 4; ++r)
#pragma unroll
        for (int c = 0; c < 4; ++c) {
            int row = ty * 4 + r;
            int col = j0 + tx * 2 + 32 * c;
            *(ull*)(&P[(size_t)row * UU + col]) = acc[r][c];
        }
}

// ---------------- reduce partials, 4-way plane split + atomics ---------------
// grid (128, 4), block 256: quarter q sums planes [q*11, min(43,q*11+11))
__global__ void reduce_split() {
    int i = blockIdx.x * blockDim.x + threadIdx.x;   // 0..32767
    int q = blockIdx.y;
    int pbeg = q * 11, pend = min(NCHUNK, pbeg + 11);
    float s1 = 0.f, s2 = 0.f;
    for (int p = pbeg; p < pend; ++p) {
        s1 += d_p1[(size_t)p * BB * UU + i];
        s2 += d_p2[(size_t)p * BB * UU + i];
    }
    atomicAdd(&d_h1[i], s1);
    atomicAdd(&d_c2[i], s2);
}

// elu in place: h1 = elu(h1 + b1). grid 128, block 256
__global__ void elu_kernel(const float* __restrict__ b1) {
    int i = blockIdx.x * blockDim.x + threadIdx.x;
    float v = d_h1[i] + b1[i & 511];
    d_h1[i] = v > 0.f ? v : expm1f(v);
}

// ---------------- 64xN GEMM core (atomic version, for small GEMMs) ----------
#define KC 16
__device__ __forceinline__ void gemm_core(const float* __restrict__ A, int lda,
                                          const float* __restrict__ W,
                                          float* __restrict__ C,
                                          int kbeg, int kend) {
    __shared__ __align__(16) float As[64][20];
    __shared__ __align__(16) float Ws[KC][128];
    int tid = threadIdx.x;
    int tx = tid & 15, ty = tid >> 4;
    int j0 = blockIdx.x * 128;
    int arow = tid >> 2, akq = (tid & 3) * 4;
    int wkk = tid >> 5, wjq = (tid & 31) * 4;
    ull acc[4][4];
#pragma unroll
    for (int r = 0; r < 4; ++r)
#pragma unroll
        for (int c = 0; c < 4; ++c) acc[r][c] = 0ULL;

    {
        float4 va = *(const float4*)(A + (size_t)arow * lda + kbeg + akq);
        float4 w0 = *(const float4*)(W + (size_t)(kbeg + wkk)     * UU + j0 + wjq);
        float4 w1 = *(const float4*)(W + (size_t)(kbeg + wkk + 8) * UU + j0 + wjq);
        *(float4*)&As[arow][akq]   = va;
        *(float4*)&Ws[wkk][wjq]    = w0;
        *(float4*)&Ws[wkk + 8][wjq] = w1;
    }
    __syncthreads();
    for (int k0 = kbeg; k0 < kend; k0 += KC) {
        float4 va, w0, w1;
        bool more = (k0 + KC) < kend;
        if (more) {
            int kn = k0 + KC;
            va = *(const float4*)(A + (size_t)arow * lda + kn + akq);
            w0 = *(const float4*)(W + (size_t)(kn + wkk)     * UU + j0 + wjq);
            w1 = *(const float4*)(W + (size_t)(kn + wkk + 8) * UU + j0 + wjq);
        }
#pragma unroll
        for (int kk = 0; kk < KC; ++kk) {
            const ull* wp = (const ull*)(&Ws[kk][tx * 8]);
            ull w2[4];
#pragma unroll
            for (int c = 0; c < 4; ++c) w2[c] = wp[c];
#pragma unroll
            for (int r = 0; r < 4; ++r) {
                ull asp = splat2(As[ty * 4 + r][kk]);
#pragma unroll
                for (int c = 0; c < 4; ++c) fma2(acc[r][c], asp, w2[c]);
            }
        }
        __syncthreads();
        if (more) {
            *(float4*)&As[arow][akq]    = va;
            *(float4*)&Ws[wkk][wjq]     = w0;
            *(float4*)&Ws[wkk + 8][wjq] = w1;
        }
        __syncthreads();
    }
#pragma unroll
    for (int r = 0; r < 4; ++r)
#pragma unroll
        for (int c = 0; c < 4; ++c) {
            float lo, hi; unpack2(acc[r][c], lo, hi);
            int row = ty * 4 + r;
            int col = j0 + tx * 8 + 2 * c;
            atomicAdd(&C[(size_t)row * UU + col], lo);
            atomicAdd(&C[(size_t)row * UU + col + 1], hi);
        }
}

__global__ void gemm_one(const float* __restrict__ A, int lda,
                         const float* __restrict__ W,
                         float* __restrict__ C, int K) {
    int kchunk = K / gridDim.y;
    gemm_core(A, lda, W, C, kchunk * blockIdx.y, kchunk * (blockIdx.y + 1));
}

__global__ void gemm_two(const float* __restrict__ A, int lda,
                         const float* __restrict__ W1, const float* __restrict__ W2,
                         float* __restrict__ C1, float* __restrict__ C2, int K) {
    int kchunk = K / gridDim.y;
    const float* W = blockIdx.z ? W2 : W1;
    float* C = blockIdx.z ? C2 : C1;
    gemm_core(A, lda, W, C, kchunk * blockIdx.y, kchunk * (blockIdx.y + 1));
}

__global__ void gemm_gates(const float* __restrict__ cur,
                           const float* __restrict__ hprev,
                           const float* __restrict__ wf, const float* __restrict__ wi,
                           const float* __restrict__ wc, const float* __restrict__ wo,
                           float* __restrict__ g4) {
    int kb = blockIdx.y * 128, ke = kb + 128;
    const float* Wg = (blockIdx.z == 0) ? wf : (blockIdx.z == 1) ? wi
                    : (blockIdx.z == 2) ? wc : wo;
    const float* A = (kb < 512) ? cur : (hprev - 512);
    gemm_core(A, UU, Wg, g4 + (size_t)blockIdx.z * BB * UU, kb, ke);
}

// ---------------- agg + inlined GLU/LN/softmax -------------------------------
// grid (64 b, 8 s-chunks), block 128. Each CTA redoes the cheap LN+softmax
// for its batch row (deterministic, removes lnsm kernel + attn round-trip).
__global__ void agg_kernel(const float* __restrict__ in,
                           const float* __restrict__ tk,
                           const float* __restrict__ b3,
                           const float* __restrict__ b4,
                           const float* __restrict__ bskip,
                           const float* __restrict__ gamma,
                           const float* __restrict__ beta) {
    __shared__ float ys[UU];
    __shared__ float red[128];
    __shared__ float ws[64], tks[64];
    int b = blockIdx.x;
    int s0 = blockIdx.y * 64;
    int tid = threadIdx.x;

    // GLU
    float y[4];
#pragma unroll
    for (int q = 0; q < 4; ++q) {
        int u = tid + 128 * q, i = b * UU + u;
        float g = sigm(d_t3[i] + b3[u]);
        y[q] = d_c2[i] + bskip[u] + g * (d_t4[i] + b4[u]);
    }
    // mean
    red[tid] = y[0] + y[1] + y[2] + y[3];
    __syncthreads();
    for (int s = 64; s > 0; s >>= 1) { if (tid < s) red[tid] += red[tid + s]; __syncthreads(); }
    float mu = red[0] * (1.f / 512.f);
    __syncthreads();
    // var
    float v = 0.f;
#pragma unroll
    for (int q = 0; q < 4; ++q) { float d = y[q] - mu; v += d * d; }
    red[tid] = v;
    __syncthreads();
    for (int s = 64; s > 0; s >>= 1) { if (tid < s) red[tid] += red[tid + s]; __syncthreads(); }
    float rs = rsqrtf(red[0] * (1.f / 512.f) + 1e-3f);
    __syncthreads();
    // normalized values + max
    float m = -1e30f;
#pragma unroll
    for (int q = 0; q < 4; ++q) {
        int u = tid + 128 * q;
        float yn = (y[q] - mu) * rs * gamma[u] + beta[u];
        ys[u] = yn;
        m = fmaxf(m, yn);
    }
    red[tid] = m;
    __syncthreads();
    for (int s = 64; s > 0; s >>= 1) { if (tid < s) red[tid] = fmaxf(red[tid], red[tid + s]); __syncthreads(); }
    float M = red[0];
    __syncthreads();
    // exp sum
    float es = 0.f;
#pragma unroll
    for (int q = 0; q < 4; ++q) es += __expf(ys[tid + 128 * q] - M);
    red[tid] = es;
    __syncthreads();
    for (int s = 64; s > 0; s >>= 1) { if (tid < s) red[tid] += red[tid + s]; __syncthreads(); }
    float inv = __fdividef(1.f, red[0] * 512.f);   // softmax / S

    if (tid < 64) {
        ws[tid]  = __expf(ys[s0 + tid] - M) * inv;
        tks[tid] = tk[s0 + tid];
    }
    __syncthreads();

    // aggregation
    int f = tid;
    float sacc = 0.f;
    float bacc[8] = {};
    const float* ip = in + (size_t)b * SS * FF + (size_t)s0 * FF + f;
    for (int si = 0; si < 64; ++si) {
        float x = tks[si] * ip[si * FF];
        float w = ws[si];
        float sg = sigm(x);
        sacc += w * (x * sg);
        float bs[8];
        bspline8(x, bs);
#pragma unroll
        for (int k = 0; k < 8; ++k) bacc[k] += w * bs[k];
    }
    atomicAdd(&d_agg[b * KCAT + f], sacc);
#pragma unroll
    for (int k = 0; k < 8; ++k)
        atomicAdd(&d_agg[b * KCAT + 128 + f * 8 + k], bacc[k]);
}

// ---------------- final LSTM cell ----------------
__global__ void lstm_kernel(const float* __restrict__ c_prev,
                            const float* __restrict__ bf,
                            const float* __restrict__ bi_,
                            const float* __restrict__ bc,
                            const float* __restrict__ bo,
                            float* __restrict__ out) {
    int i = blockIdx.x * blockDim.x + threadIdx.x;
    int u = i & 511;
    float f  = sigm(d_g4[i]            + bf [u]);
    float ig = sigm(d_g4[BB*UU + i]    + bi_[u]);
    float cd = tanhf(d_g4[2*BB*UU + i] + bc [u]);
    float o  = sigm(d_g4[3*BB*UU + i]  + bo [u]);
    float cn = f * c_prev[i] + ig * cd;
    out[i] = o * tanhf(cn);
    out[BB*UU + i] = cn;
}

// ---------------- host ----------------
extern "C" void kernel_launch(void* const* d_in, const int* in_sizes, int n_in,
                              void* d_out, int out_size) {
    const float* in       = (const float*)d_in[0];
    const float* h_prev   = (const float*)d_in[1];
    const float* c_prev   = (const float*)d_in[2];
    const float* tk       = (const float*)d_in[3];
    const float* base_w   = (const float*)d_in[4];
    const float* spline_w = (const float*)d_in[5];
    const float* g_w1     = (const float*)d_in[6];
    const float* g_b1     = (const float*)d_in[7];
    const float* g_w2     = (const float*)d_in[8];
    const float* g_b2     = (const float*)d_in[9];
    const float* g_w3     = (const float*)d_in[10];
    const float* g_b3     = (const float*)d_in[11];
    const float* g_w4     = (const float*)d_in[12];
    const float* g_b4     = (const float*)d_in[13];
    const float* g_skip_w = (const float*)d_in[14];
    const float* g_skip_b = (const float*)d_in[15];
    const float* ln_gamma = (const float*)d_in[16];
    const float* ln_beta  = (const float*)d_in[17];
    const float* wf       = (const float*)d_in[18];
    const float* bf       = (const float*)d_in[19];
    const float* wi       = (const float*)d_in[20];
    const float* bi       = (const float*)d_in[21];
    const float* wc       = (const float*)d_in[22];
    const float* bc       = (const float*)d_in[23];
    const float* wo       = (const float*)d_in[24];
    const float* bo       = (const float*)d_in[25];
    float* out = (float*)d_out;
    (void)in_sizes; (void)n_in; (void)out_size;

    float *p_sig, *p_p1, *p_p2, *p_h1, *p_h2, *p_t3, *p_t4;
    float *p_agg, *p_cur, *p_Wcat, *p_g4;
    cudaGetSymbolAddress((void**)&p_sig,  d_sig);
    cudaGetSymbolAddress((void**)&p_p1,   d_p1);
    cudaGetSymbolAddress((void**)&p_p2,   d_p2);
    cudaGetSymbolAddress((void**)&p_h1,   d_h1);
    cudaGetSymbolAddress((void**)&p_h2,   d_h2);
    cudaGetSymbolAddress((void**)&p_t3,   d_t3);
    cudaGetSymbolAddress((void**)&p_t4,   d_t4);
    cudaGetSymbolAddress((void**)&p_agg,  d_agg);
    cudaGetSymbolAddress((void**)&p_cur,  d_cur);
    cudaGetSymbolAddress((void**)&p_Wcat, d_Wcat);
    cudaGetSymbolAddress((void**)&p_g4,   d_g4);

    init_kernel<<<1560, 256>>>(g_b2, spline_w, base_w);
    s2p_kernel<<<dim3(64, 4), 256>>>(in, tk);

    // sig @ g_w1 and sig @ g_skip_w -> partial planes (344 CTAs, single wave)
    gemm_sig<<<dim3(4, NCHUNK, 2), 256>>>(p_sig, g_w1, g_skip_w, p_p1, p_p2);
    reduce_split<<<dim3(128, 4), 256>>>();
    elu_kernel<<<128, 256>>>(g_b1);

    gemm_one<<<dim3(4, 32), 256>>>(p_h1, UU, g_w2, p_h2, UU);           // h2 += h1@W2 (b2 pre-set)
    gemm_two<<<dim3(4, 16, 2), 256>>>(p_h2, UU, g_w3, g_w4, p_t3, p_t4, UU);

    agg_kernel<<<dim3(64, 8), 128>>>(in, tk, g_b3, g_b4, g_skip_b, ln_gamma, ln_beta);

    // current = [aggs|aggb] @ [base_w; spline_w^T]  (K=1152, 12 chunks of 96)
    gemm_one<<<dim3(4, 12), 256>>>(p_agg, KCAT, p_Wcat, p_cur, KCAT);

    // gates: combined = [current | h_prev], kchunk 128
    gemm_gates<<<dim3(4, 8, 4), 256>>>(p_cur, h_prev, wf, wi, wc, wo, p_g4);

    lstm_kernel<<<128, 256>>>(c_prev, bf, bi, bc, bo, out);
}

// round 15
// speedup vs baseline: 1.5406x; 1.0106x over previous
#include <cuda_runtime.h>
#include <math.h>

#define BB 64
#define SS 512
#define FF 128
#define UU 512
#define TT 511            // S-1
#define SIGD 16512        // F + F*F
#define KCAT 1152         // 128 (base) + 1024 (spline)
#define NCHUNK 37         // sig GEMM K-split: 36 chunks of 448 + 1 of 384
#define KCH 448

typedef unsigned long long ull;

// ---------------- scratch (static device memory; no allocations) ----------------
static __device__ float d_sig [BB*SIGD];    // [s1 | s2]
static __device__ float d_p1  [NCHUNK*BB*UU];  // sig@g_w1 partials (4.8 MB)
static __device__ float d_p2  [NCHUNK*BB*UU];  // sig@g_skip_w partials
static __device__ float d_c2  [BB*UU];
static __device__ float d_h1  [BB*UU];
static __device__ float d_h2  [BB*UU];
static __device__ float d_t3  [BB*UU];
static __device__ float d_t4  [BB*UU];
static __device__ float d_agg [BB*KCAT];    // [sum w*silu(x) | sum w*bspl(x)]
static __device__ float d_cur [BB*UU];
static __device__ float d_Wcat[KCAT*UU];    // [base_w ; spline_w^T]
static __device__ float d_g4  [4*BB*UU];    // gates f,i,c,o pre-activation

// ---------------- helpers ----------------
__device__ __forceinline__ float sigm(float x) {
    return __fdividef(1.f, 1.f + __expf(-x));
}
__device__ __forceinline__ void fma2(ull &d, ull a, ull b) {
    asm("fma.rn.f32x2 %0, %1, %2, %0;" : "+l"(d) : "l"(a), "l"(b));
}
__device__ __forceinline__ ull splat2(float x) {
    ull r; asm("mov.b64 %0, {%1, %1};" : "=l"(r) : "f"(x)); return r;
}
__device__ __forceinline__ void unpack2(ull v, float &lo, float &hi) {
    asm("mov.b64 {%0, %1}, %2;" : "=f"(lo), "=f"(hi) : "l"(v));
}

// cubic B-spline basis (GRID_SIZE=5, ORDER=3); denominators constant-fold
__device__ __forceinline__ void bspline8(float x, float bs[8]) {
    float g[12];
#pragma unroll
    for (int j = 0; j < 12; ++j) g[j] = -1.0f + 0.4f * (float)(j - 3);
    float b0[11];
#pragma unroll
    for (int j = 0; j < 11; ++j) b0[j] = (x >= g[j] && x < g[j + 1]) ? 1.f : 0.f;
#pragma unroll
    for (int p = 1; p <= 3; ++p) {
#pragma unroll
        for (int j = 0; j + p < 11; ++j) {
            float left  = (x - g[j])       * (1.0f / (g[j + p] - g[j]));
            float right = (g[j + p + 1]-x) * (1.0f / (g[j + p + 1] - g[j + 1]));
            b0[j] = left * b0[j] + right * b0[j + 1];
        }
    }
#pragma unroll
    for (int k = 0; k < 8; ++k) bs[k] = b0[k];
}

// ---------------- merged init: zero + h2<-b2 + Wcat build ----------------
// grid 1560 blocks of 256: [0,1032) zero, [1032,1544) transpose, [1544,1560) copy
__global__ void init_kernel(const float* __restrict__ b2,
                            const float* __restrict__ sw,
                            const float* __restrict__ bw) {
    __shared__ float tile[32][33];
    int bid = blockIdx.x;
    if (bid < 1032) {
        int i = bid * 256 + threadIdx.x;
        float4 z = make_float4(0.f, 0.f, 0.f, 0.f);
        if (i < BB * SIGD / 4) ((float4*)d_sig)[i] = z;
        if (i < BB * UU / 4) {
            ((float4*)d_t3)[i] = z; ((float4*)d_t4)[i] = z; ((float4*)d_cur)[i] = z;
            ((float4*)d_c2)[i] = z; ((float4*)d_h1)[i] = z;
        }
        if (i < 4 * BB * UU / 4) ((float4*)d_g4)[i] = z;
        if (i < BB * KCAT / 4) ((float4*)d_agg)[i] = z;
        if (i < BB * UU) d_h2[i] = b2[i & 511];
    } else {
        int pid = bid - 1032;
        int tx = threadIdx.x & 31, ty = threadIdx.x >> 5;
        if (pid < 512) {
            int fk0 = (pid & 31) * 32, u0 = (pid >> 5) * 32;
            for (int r = ty; r < 32; r += 8)
                tile[r][tx] = sw[(size_t)(u0 + r) * 1024 + fk0 + tx];
            __syncthreads();
            for (int r = ty; r < 32; r += 8)
                d_Wcat[(size_t)(128 + fk0 + r) * UU + u0 + tx] = tile[tx][r];
        } else {
            int base = (pid - 512) * 4096;
            for (int i = threadIdx.x; i < 4096; i += 256)
                d_Wcat[base + i] = bw[base + i];
        }
    }
}

// ---------------- scan-free signature kernel (full 128-col tiles) ------------
// A_t = 0.5(x_t + x_{t+1}) - x_0 ; B_t = x_{t+1} - x_t ; s2 += A_t (x) B_t
// grid (64 b, 4 tseg), block 256; per-thread 8 rows (4 f32x2 pairs) x 8 cols
__global__ void s2p_kernel(const float* __restrict__ in,
                           const float* __restrict__ tk) {
    __shared__ __align__(16) float xc[16][FF];
    __shared__ __align__(16) float Ak[16][FF];
    __shared__ __align__(16) float Bk[16][FF];
    __shared__ float x0s[FF], xprev[FF];
    __shared__ float tks[SS];
    int b  = blockIdx.x;
    int t0 = blockIdx.y * 128;
    int tlim = min(TT, t0 + 128);
    int tid = threadIdx.x;
    int tx = tid & 15, ty = tid >> 4;
    const float* ib = in + (size_t)b * SS * FF;

    for (int i = tid; i < SS; i += 256) tks[i] = tk[i];
    __syncthreads();
    if (tid < FF) {
        x0s[tid]   = tks[0]  * ib[tid];
        xprev[tid] = tks[t0] * ib[(size_t)t0 * FF + tid];
    }
    __syncthreads();

    ull acc[4][8];
#pragma unroll
    for (int r = 0; r < 4; ++r)
#pragma unroll
        for (int c = 0; c < 8; ++c) acc[r][c] = 0ULL;

    for (int cch = 0; cch < 8; ++cch) {
        int tbase = t0 + cch * 16;
#pragma unroll
        for (int s = 0; s < 8; ++s) {
            int e = tid + s * 256;
            int kk = e >> 7, f = e & 127;
            int t1 = tbase + kk + 1;
            xc[kk][f] = (t1 < SS) ? tks[t1] * ib[(size_t)t1 * FF + f] : 0.f;
        }
        __syncthreads();
#pragma unroll
        for (int s = 0; s < 8; ++s) {
            int e = tid + s * 256;
            int kk = e >> 7, f = e & 127;
            float prev = kk ? xc[kk - 1][f] : xprev[f];
            float cur = xc[kk][f];
            bool valid = (tbase + kk) < tlim;
            Bk[kk][f] = valid ? (cur - prev) : 0.f;
            Ak[kk][f] = 0.5f * (prev + cur) - x0s[f];
        }
        if (tid < FF) xprev[tid] = xc[15][tid];
        __syncthreads();
#pragma unroll
        for (int kk = 0; kk < 16; ++kk) {
            const ull* ap = (const ull*)(&Ak[kk][ty * 8]);
            ull a2[4];
#pragma unroll
            for (int r = 0; r < 4; ++r) a2[r] = ap[r];
#pragma unroll
            for (int c = 0; c < 8; ++c) {
                ull dsp = splat2(Bk[kk][tx + 16 * c]);
#pragma unroll
                for (int r = 0; r < 4; ++r) fma2(acc[r][c], a2[r], dsp);
            }
        }
        __syncthreads();
    }

    float* out = d_sig + (size_t)b * SIGD + FF;
#pragma unroll
    for (int r = 0; r < 4; ++r)
#pragma unroll
        for (int c = 0; c < 8; ++c) {
            float lo, hi; unpack2(acc[r][c], lo, hi);
            int i = ty * 8 + 2 * r;
            int j = tx + 16 * c;
            atomicAdd(&out[(size_t)i * FF + j], lo);
            atomicAdd(&out[(size_t)(i + 1) * FF + j], hi);
        }
    // s1 = x[S-1] - x[0]
    if (blockIdx.y == 0 && tid < FF)
        d_sig[(size_t)b * SIGD + tid] = tks[SS - 1] * ib[(size_t)(SS - 1) * FF + tid] - x0s[tid];
}

// ---------------- sig GEMM: single-buffer, 296-CTA balanced wave -------------
// grid (4 jtile, 37 kchunk, 2 which) = 296 CTAs = exactly 2/SM, even wave.
// Chunks: 36 x 448 k + 1 x 384 k (all multiples of 16).
__global__ void __launch_bounds__(256, 2)
gemm_sig(const float* __restrict__ A,
         const float* __restrict__ W1, const float* __restrict__ W2,
         float* __restrict__ P1, float* __restrict__ P2) {
    __shared__ __align__(16) ull  As2[64][18];
    __shared__ __align__(16) float Ws[16][128];
    int tid = threadIdx.x;
    int tx = tid & 15, ty = tid >> 4;
    int j0 = blockIdx.x * 128;
    int kbeg = blockIdx.y * KCH;
    int kend = min(SIGD, kbeg + KCH);
    const float* W = blockIdx.z ? W2 : W1;
    float* P = (blockIdx.z ? P2 : P1) + (size_t)blockIdx.y * BB * UU;
    int arow = tid >> 2, akq = (tid & 3) * 4;
    int wkk = tid >> 5, wjq = (tid & 31) * 4;

    ull acc[4][4];
#pragma unroll
    for (int r = 0; r < 4; ++r)
#pragma unroll
        for (int c = 0; c < 4; ++c) acc[r][c] = 0ULL;

    {
        float4 va = *(const float4*)(A + (size_t)arow * SIGD + kbeg + akq);
        float4 w0 = *(const float4*)(W + (size_t)(kbeg + wkk)     * UU + j0 + wjq);
        float4 w1 = *(const float4*)(W + (size_t)(kbeg + wkk + 8) * UU + j0 + wjq);
        As2[arow][akq]     = splat2(va.x);
        As2[arow][akq + 1] = splat2(va.y);
        As2[arow][akq + 2] = splat2(va.z);
        As2[arow][akq + 3] = splat2(va.w);
        *(float4*)&Ws[wkk][wjq]     = w0;
        *(float4*)&Ws[wkk + 8][wjq] = w1;
    }
    __syncthreads();
    for (int k0 = kbeg; k0 < kend; k0 += 16) {
        float4 va, w0, w1;
        bool more = (k0 + 16) < kend;
        if (more) {
            int kn = k0 + 16;
            va = *(const float4*)(A + (size_t)arow * SIGD + kn + akq);
            w0 = *(const float4*)(W + (size_t)(kn + wkk)     * UU + j0 + wjq);
            w1 = *(const float4*)(W + (size_t)(kn + wkk + 8) * UU + j0 + wjq);
        }
#pragma unroll
        for (int kk = 0; kk < 16; ++kk) {
            ull w2[4];
#pragma unroll
            for (int c = 0; c < 4; ++c)
                w2[c] = *(const ull*)(&Ws[kk][tx * 2 + 32 * c]);
#pragma unroll
            for (int r = 0; r < 4; ++r) {
                ull asp = As2[ty * 4 + r][kk];
#pragma unroll
                for (int c = 0; c < 4; ++c) fma2(acc[r][c], asp, w2[c]);
            }
        }
        __syncthreads();
        if (more) {
            As2[arow][akq]     = splat2(va.x);
            As2[arow][akq + 1] = splat2(va.y);
            As2[arow][akq + 2] = splat2(va.z);
            As2[arow][akq + 3] = splat2(va.w);
            *(float4*)&Ws[wkk][wjq]     = w0;
            *(float4*)&Ws[wkk + 8][wjq] = w1;
        }
        __syncthreads();
    }
#pragma unroll
    for (int r = 0; r < 4; ++r)
#pragma unroll
        for (int c = 0; c < 4; ++c) {
            int row = ty * 4 + r;
            int col = j0 + tx * 2 + 32 * c;
            *(ull*)(&P[(size_t)row * UU + col]) = acc[r][c];
        }
}

// ---------------- reduce partials, 4-way plane split + atomics ---------------
// grid (128, 4), block 256: quarter q sums planes [q*10, min(37,q*10+10))
__global__ void reduce_split() {
    int i = blockIdx.x * blockDim.x + threadIdx.x;   // 0..32767
    int q = blockIdx.y;
    int pbeg = q * 10, pend = min(NCHUNK, pbeg + 10);
    float s1 = 0.f, s2 = 0.f;
    for (int p = pbeg; p < pend; ++p) {
        s1 += d_p1[(size_t)p * BB * UU + i];
        s2 += d_p2[(size_t)p * BB * UU + i];
    }
    atomicAdd(&d_h1[i], s1);
    atomicAdd(&d_c2[i], s2);
}

// elu in place: h1 = elu(h1 + b1). grid 128, block 256
__global__ void elu_kernel(const float* __restrict__ b1) {
    int i = blockIdx.x * blockDim.x + threadIdx.x;
    float v = d_h1[i] + b1[i & 511];
    d_h1[i] = v > 0.f ? v : expm1f(v);
}

// ---------------- 64xN GEMM core (atomic version, for small GEMMs) ----------
#define KC 16
__device__ __forceinline__ void gemm_core(const float* __restrict__ A, int lda,
                                          const float* __restrict__ W,
                                          float* __restrict__ C,
                                          int kbeg, int kend) {
    __shared__ __align__(16) float As[64][20];
    __shared__ __align__(16) float Ws[KC][128];
    int tid = threadIdx.x;
    int tx = tid & 15, ty = tid >> 4;
    int j0 = blockIdx.x * 128;
    int arow = tid >> 2, akq = (tid & 3) * 4;
    int wkk = tid >> 5, wjq = (tid & 31) * 4;
    ull acc[4][4];
#pragma unroll
    for (int r = 0; r < 4; ++r)
#pragma unroll
        for (int c = 0; c < 4; ++c) acc[r][c] = 0ULL;

    {
        float4 va = *(const float4*)(A + (size_t)arow * lda + kbeg + akq);
        float4 w0 = *(const float4*)(W + (size_t)(kbeg + wkk)     * UU + j0 + wjq);
        float4 w1 = *(const float4*)(W + (size_t)(kbeg + wkk + 8) * UU + j0 + wjq);
        *(float4*)&As[arow][akq]   = va;
        *(float4*)&Ws[wkk][wjq]    = w0;
        *(float4*)&Ws[wkk + 8][wjq] = w1;
    }
    __syncthreads();
    for (int k0 = kbeg; k0 < kend; k0 += KC) {
        float4 va, w0, w1;
        bool more = (k0 + KC) < kend;
        if (more) {
            int kn = k0 + KC;
            va = *(const float4*)(A + (size_t)arow * lda + kn + akq);
            w0 = *(const float4*)(W + (size_t)(kn + wkk)     * UU + j0 + wjq);
            w1 = *(const float4*)(W + (size_t)(kn + wkk + 8) * UU + j0 + wjq);
        }
#pragma unroll
        for (int kk = 0; kk < KC; ++kk) {
            const ull* wp = (const ull*)(&Ws[kk][tx * 8]);
            ull w2[4];
#pragma unroll
            for (int c = 0; c < 4; ++c) w2[c] = wp[c];
#pragma unroll
            for (int r = 0; r < 4; ++r) {
                ull asp = splat2(As[ty * 4 + r][kk]);
#pragma unroll
                for (int c = 0; c < 4; ++c) fma2(acc[r][c], asp, w2[c]);
            }
        }
        __syncthreads();
        if (more) {
            *(float4*)&As[arow][akq]    = va;
            *(float4*)&Ws[wkk][wjq]     = w0;
            *(float4*)&Ws[wkk + 8][wjq] = w1;
        }
        __syncthreads();
    }
#pragma unroll
    for (int r = 0; r < 4; ++r)
#pragma unroll
        for (int c = 0; c < 4; ++c) {
            float lo, hi; unpack2(acc[r][c], lo, hi);
            int row = ty * 4 + r;
            int col = j0 + tx * 8 + 2 * c;
            atomicAdd(&C[(size_t)row * UU + col], lo);
            atomicAdd(&C[(size_t)row * UU + col + 1], hi);
        }
}

__global__ void gemm_one(const float* __restrict__ A, int lda,
                         const float* __restrict__ W,
                         float* __restrict__ C, int K) {
    int kchunk = K / gridDim.y;
    gemm_core(A, lda, W, C, kchunk * blockIdx.y, kchunk * (blockIdx.y + 1));
}

__global__ void gemm_two(const float* __restrict__ A, int lda,
                         const float* __restrict__ W1, const float* __restrict__ W2,
                         float* __restrict__ C1, float* __restrict__ C2, int K) {
    int kchunk = K / gridDim.y;
    const float* W = blockIdx.z ? W2 : W1;
    float* C = blockIdx.z ? C2 : C1;
    gemm_core(A, lda, W, C, kchunk * blockIdx.y, kchunk * (blockIdx.y + 1));
}

__global__ void gemm_gates(const float* __restrict__ cur,
                           const float* __restrict__ hprev,
                           const float* __restrict__ wf, const float* __restrict__ wi,
                           const float* __restrict__ wc, const float* __restrict__ wo,
                           float* __restrict__ g4) {
    int kb = blockIdx.y * 128, ke = kb + 128;
    const float* Wg = (blockIdx.z == 0) ? wf : (blockIdx.z == 1) ? wi
                    : (blockIdx.z == 2) ? wc : wo;
    const float* A = (kb < 512) ? cur : (hprev - 512);
    gemm_core(A, UU, Wg, g4 + (size_t)blockIdx.z * BB * UU, kb, ke);
}

// ---------------- agg + inlined GLU/LN/softmax -------------------------------
// grid (64 b, 8 s-chunks), block 128. Each CTA redoes the cheap LN+softmax
// for its batch row (deterministic, removes lnsm kernel + attn round-trip).
__global__ void agg_kernel(const float* __restrict__ in,
                           const float* __restrict__ tk,
                           const float* __restrict__ b3,
                           const float* __restrict__ b4,
                           const float* __restrict__ bskip,
                           const float* __restrict__ gamma,
                           const float* __restrict__ beta) {
    __shared__ float ys[UU];
    __shared__ float red[128];
    __shared__ float ws[64], tks[64];
    int b = blockIdx.x;
    int s0 = blockIdx.y * 64;
    int tid = threadIdx.x;

    // GLU
    float y[4];
#pragma unroll
    for (int q = 0; q < 4; ++q) {
        int u = tid + 128 * q, i = b * UU + u;
        float g = sigm(d_t3[i] + b3[u]);
        y[q] = d_c2[i] + bskip[u] + g * (d_t4[i] + b4[u]);
    }
    // mean
    red[tid] = y[0] + y[1] + y[2] + y[3];
    __syncthreads();
    for (int s = 64; s > 0; s >>= 1) { if (tid < s) red[tid] += red[tid + s]; __syncthreads(); }
    float mu = red[0] * (1.f / 512.f);
    __syncthreads();
    // var
    float v = 0.f;
#pragma unroll
    for (int q = 0; q < 4; ++q) { float d = y[q] - mu; v += d * d; }
    red[tid] = v;
    __syncthreads();
    for (int s = 64; s > 0; s >>= 1) { if (tid < s) red[tid] += red[tid + s]; __syncthreads(); }
    float rs = rsqrtf(red[0] * (1.f / 512.f) + 1e-3f);
    __syncthreads();
    // normalized values + max
    float m = -1e30f;
#pragma unroll
    for (int q = 0; q < 4; ++q) {
        int u = tid + 128 * q;
        float yn = (y[q] - mu) * rs * gamma[u] + beta[u];
        ys[u] = yn;
        m = fmaxf(m, yn);
    }
    red[tid] = m;
    __syncthreads();
    for (int s = 64; s > 0; s >>= 1) { if (tid < s) red[tid] = fmaxf(red[tid], red[tid + s]); __syncthreads(); }
    float M = red[0];
    __syncthreads();
    // exp sum
    float es = 0.f;
#pragma unroll
    for (int q = 0; q < 4; ++q) es += __expf(ys[tid + 128 * q] - M);
    red[tid] = es;
    __syncthreads();
    for (int s = 64; s > 0; s >>= 1) { if (tid < s) red[tid] += red[tid + s]; __syncthreads(); }
    float inv = __fdividef(1.f, red[0] * 512.f);   // softmax / S

    if (tid < 64) {
        ws[tid]  = __expf(ys[s0 + tid] - M) * inv;
        tks[tid] = tk[s0 + tid];
    }
    __syncthreads();

    // aggregation
    int f = tid;
    float sacc = 0.f;
    float bacc[8] = {};
    const float* ip = in + (size_t)b * SS * FF + (size_t)s0 * FF + f;
    for (int si = 0; si < 64; ++si) {
        float x = tks[si] * ip[si * FF];
        float w = ws[si];
        float sg = sigm(x);
        sacc += w * (x * sg);
        float bs[8];
        bspline8(x, bs);
#pragma unroll
        for (int k = 0; k < 8; ++k) bacc[k] += w * bs[k];
    }
    atomicAdd(&d_agg[b * KCAT + f], sacc);
#pragma unroll
    for (int k = 0; k < 8; ++k)
        atomicAdd(&d_agg[b * KCAT + 128 + f * 8 + k], bacc[k]);
}

// ---------------- final LSTM cell ----------------
__global__ void lstm_kernel(const float* __restrict__ c_prev,
                            const float* __restrict__ bf,
                            const float* __restrict__ bi_,
                            const float* __restrict__ bc,
                            const float* __restrict__ bo,
                            float* __restrict__ out) {
    int i = blockIdx.x * blockDim.x + threadIdx.x;
    int u = i & 511;
    float f  = sigm(d_g4[i]            + bf [u]);
    float ig = sigm(d_g4[BB*UU + i]    + bi_[u]);
    float cd = tanhf(d_g4[2*BB*UU + i] + bc [u]);
    float o  = sigm(d_g4[3*BB*UU + i]  + bo [u]);
    float cn = f * c_prev[i] + ig * cd;
    out[i] = o * tanhf(cn);
    out[BB*UU + i] = cn;
}

// ---------------- host ----------------
extern "C" void kernel_launch(void* const* d_in, const int* in_sizes, int n_in,
                              void* d_out, int out_size) {
    const float* in       = (const float*)d_in[0];
    const float* h_prev   = (const float*)d_in[1];
    const float* c_prev   = (const float*)d_in[2];
    const float* tk       = (const float*)d_in[3];
    const float* base_w   = (const float*)d_in[4];
    const float* spline_w = (const float*)d_in[5];
    const float* g_w1     = (const float*)d_in[6];
    const float* g_b1     = (const float*)d_in[7];
    const float* g_w2     = (const float*)d_in[8];
    const float* g_b2     = (const float*)d_in[9];
    const float* g_w3     = (const float*)d_in[10];
    const float* g_b3     = (const float*)d_in[11];
    const float* g_w4     = (const float*)d_in[12];
    const float* g_b4     = (const float*)d_in[13];
    const float* g_skip_w = (const float*)d_in[14];
    const float* g_skip_b = (const float*)d_in[15];
    const float* ln_gamma = (const float*)d_in[16];
    const float* ln_beta  = (const float*)d_in[17];
    const float* wf       = (const float*)d_in[18];
    const float* bf       = (const float*)d_in[19];
    const float* wi       = (const float*)d_in[20];
    const float* bi       = (const float*)d_in[21];
    const float* wc       = (const float*)d_in[22];
    const float* bc       = (const float*)d_in[23];
    const float* wo       = (const float*)d_in[24];
    const float* bo       = (const float*)d_in[25];
    float* out = (float*)d_out;
    (void)in_sizes; (void)n_in; (void)out_size;

    float *p_sig, *p_p1, *p_p2, *p_h1, *p_h2, *p_t3, *p_t4;
    float *p_agg, *p_cur, *p_Wcat, *p_g4;
    cudaGetSymbolAddress((void**)&p_sig,  d_sig);
    cudaGetSymbolAddress((void**)&p_p1,   d_p1);
    cudaGetSymbolAddress((void**)&p_p2,   d_p2);
    cudaGetSymbolAddress((void**)&p_h1,   d_h1);
    cudaGetSymbolAddress((void**)&p_h2,   d_h2);
    cudaGetSymbolAddress((void**)&p_t3,   d_t3);
    cudaGetSymbolAddress((void**)&p_t4,   d_t4);
    cudaGetSymbolAddress((void**)&p_agg,  d_agg);
    cudaGetSymbolAddress((void**)&p_cur,  d_cur);
    cudaGetSymbolAddress((void**)&p_Wcat, d_Wcat);
    cudaGetSymbolAddress((void**)&p_g4,   d_g4);

    init_kernel<<<1560, 256>>>(g_b2, spline_w, base_w);
    s2p_kernel<<<dim3(64, 4), 256>>>(in, tk);

    // sig @ g_w1 and sig @ g_skip_w -> partial planes (296 CTAs, even 2/SM wave)
    gemm_sig<<<dim3(4, NCHUNK, 2), 256>>>(p_sig, g_w1, g_skip_w, p_p1, p_p2);
    reduce_split<<<dim3(128, 4), 256>>>();
    elu_kernel<<<128, 256>>>(g_b1);

    gemm_one<<<dim3(4, 32), 256>>>(p_h1, UU, g_w2, p_h2, UU);           // h2 += h1@W2 (b2 pre-set)
    gemm_two<<<dim3(4, 16, 2), 256>>>(p_h2, UU, g_w3, g_w4, p_t3, p_t4, UU);

    agg_kernel<<<dim3(64, 8), 128>>>(in, tk, g_b3, g_b4, g_skip_b, ln_gamma, ln_beta);

    // current = [aggs|aggb] @ [base_w; spline_w^T]  (K=1152, 12 chunks of 96)
    gemm_one<<<dim3(4, 12), 256>>>(p_agg, KCAT, p_Wcat, p_cur, KCAT);

    // gates: combined = [current | h_prev], kchunk 128
    gemm_gates<<<dim3(4, 8, 4), 256>>>(p_cur, h_prev, wf, wi, wc, wo, p_g4);

    lstm_kernel<<<128, 256>>>(c_prev, bf, bi, bc, bo, out);
}